// round 2
// baseline (speedup 1.0000x reference)
#include <cuda_runtime.h>
#include <math.h>

#define N_ROWS 4096
#define C_CLS  91
#define R_ROI  1024
#define K_KP   17
#define HM     56
#define RESO   64
#define BETA   (1.0f/9.0f)

#define OFF_XY   2
#define OFF_ES   (2 + R_ROI*K_KP*3)            /* 52226 */
#define OFF_MASK (OFF_ES + R_ROI*K_KP)         /* 69634 */
#define MASK_HW  784                            /* 28*28 */

#define LOSS_BLOCKS 64
__device__ float g_partials[2 * LOSS_BLOCKS];

// ---------------------------------------------------------------------------
// Keypoints: bicubic 56->64 (jax.image.resize semantics) + argmax + coords
// One CTA per (r,k) map. HBM-bound: 12.5KB map read per CTA, 213MB total.
// ---------------------------------------------------------------------------
__global__ void __launch_bounds__(256) kp_kernel(
    const float* __restrict__ maps,   // [R,K,56,56]
    const float* __restrict__ rois,   // [R,4]
    float* __restrict__ out)
{
    __shared__ float smap[HM * HM];      // 12544 B
    __shared__ float stmp[RESO * HM];    // 14336 B  (yo-major, 56 cols)
    __shared__ int   widx[RESO * 4];
    __shared__ float wval[RESO * 4];
    __shared__ float rv[256];
    __shared__ int   ri[256];

    const int map_id = blockIdx.x;       // r*17 + k
    const int tid = threadIdx.x;
    const float* mp = maps + (size_t)map_id * (HM * HM);

    // stage map into smem (coalesced)
    for (int i = tid; i < HM * HM; i += 256) smap[i] = mp[i];

    // bicubic weight table: sample s=(i+0.5)*(56/64)-0.5, Keys a=-0.5,
    // out-of-range taps dropped, remaining renormalized to sum 1 (jax).
    if (tid < RESO) {
        float s = (tid + 0.5f) * ((float)HM / (float)RESO) - 0.5f;
        int b = (int)floorf(s);
        float w[4]; int id[4]; float wsum = 0.f;
        #pragma unroll
        for (int j = 0; j < 4; j++) {
            int k = b - 1 + j;
            float t = fabsf(s - (float)k);
            float wc;
            if (t < 1.f)      wc = ((1.5f*t - 2.5f)*t)*t + 1.f;
            else if (t < 2.f) wc = ((-0.5f*t + 2.5f)*t - 4.f)*t + 2.f;
            else              wc = 0.f;
            if (k < 0 || k >= HM) { wc = 0.f; k = 0; }
            w[j] = wc; id[j] = k; wsum += wc;
        }
        float inv = 1.f / wsum;
        #pragma unroll
        for (int j = 0; j < 4; j++) { wval[tid*4+j] = w[j]*inv; widx[tid*4+j] = id[j]; }
    }
    __syncthreads();

    // stage 1: interpolate along H (dim order matches jax: H then W)
    for (int t = tid; t < RESO * HM; t += 256) {
        int yo = t / HM, x = t - yo * HM;
        float acc = 0.f;
        #pragma unroll
        for (int j = 0; j < 4; j++)
            acc += wval[yo*4+j] * smap[widx[yo*4+j] * HM + x];
        stmp[yo * HM + x] = acc;
    }
    __syncthreads();

    // stage 2: interpolate along W, fused argmax (first-index tie-break)
    float best = -INFINITY; int bidx = 0;
    for (int p = tid; p < RESO * RESO; p += 256) {
        int yo = p >> 6, xo = p & 63;
        const float* tr = stmp + yo * HM;
        float acc = 0.f;
        #pragma unroll
        for (int j = 0; j < 4; j++)
            acc += wval[xo*4+j] * tr[widx[xo*4+j]];
        if (acc > best) { best = acc; bidx = p; }   // p ascending -> first index on tie
    }
    rv[tid] = best; ri[tid] = bidx;
    __syncthreads();
    for (int s = 128; s; s >>= 1) {
        if (tid < s) {
            float ov = rv[tid + s]; int oi = ri[tid + s];
            if (ov > rv[tid] || (ov == rv[tid] && oi < ri[tid])) { rv[tid] = ov; ri[tid] = oi; }
        }
        __syncthreads();
    }

    if (tid == 0) {
        int r = map_id / K_KP;
        float x1 = rois[r*4+0], y1 = rois[r*4+1];
        float x2 = rois[r*4+2], y2 = rois[r*4+3];
        float wc = fmaxf(x2 - x1, 1.f) / (float)RESO;
        float hc = fmaxf(y2 - y1, 1.f) / (float)RESO;
        int pos = ri[0];
        int xi = pos & 63, yi = pos >> 6;
        float* xy = out + OFF_XY + (size_t)map_id * 3;
        xy[0] = (xi + 0.5f) * wc + x1;
        xy[1] = (yi + 0.5f) * hc + y1;
        xy[2] = 1.f;
        out[OFF_ES + map_id] = rv[0];
    }
}

// ---------------------------------------------------------------------------
// Mask inference: gather selected class plane + sigmoid. 3.2MB read only.
// ---------------------------------------------------------------------------
__global__ void mask_kernel(const float* __restrict__ mlog,  // [R,91,28,28]
                            const int*   __restrict__ mlab,  // [R]
                            float* __restrict__ out)
{
    int idx = blockIdx.x * blockDim.x + threadIdx.x;
    if (idx >= R_ROI * MASK_HW) return;
    int r = idx / MASK_HW;
    int i = idx - r * MASK_HW;
    int lab = __ldg(&mlab[r]);
    float v = __ldg(&mlog[((size_t)r * C_CLS + lab) * MASK_HW + i]);
    out[OFF_MASK + idx] = 1.f / (1.f + expf(-v));
}

// ---------------------------------------------------------------------------
// FastRCNN loss: warp-per-row logsumexp + smooth-L1 gather, deterministic
// two-stage reduction (no float atomics).
// ---------------------------------------------------------------------------
__global__ void __launch_bounds__(256) loss_partial_kernel(
    const float* __restrict__ logits,  // [N,91]
    const float* __restrict__ br,      // [N,364]
    const int*   __restrict__ labels,  // [N]
    const float* __restrict__ tgt)     // [N,4]
{
    int gwarp  = (blockIdx.x * blockDim.x + threadIdx.x) >> 5;
    int lane   = threadIdx.x & 31;
    int nwarps = (gridDim.x * blockDim.x) >> 5;

    float cls_acc = 0.f, box_acc = 0.f;
    for (int row = gwarp; row < N_ROWS; row += nwarps) {
        const float* lp = logits + (size_t)row * C_CLS;
        int lab = labels[row];
        float v0 = (lane      < C_CLS) ? lp[lane]      : -INFINITY;
        float v1 = (lane + 32 < C_CLS) ? lp[lane + 32] : -INFINITY;
        float v2 = (lane + 64 < C_CLS) ? lp[lane + 64] : -INFINITY;
        float m = fmaxf(v0, fmaxf(v1, v2));
        #pragma unroll
        for (int o = 16; o; o >>= 1) m = fmaxf(m, __shfl_xor_sync(0xffffffffu, m, o));
        float s = 0.f;
        if (lane      < C_CLS) s += expf(v0 - m);
        if (lane + 32 < C_CLS) s += expf(v1 - m);
        if (lane + 64 < C_CLS) s += expf(v2 - m);
        #pragma unroll
        for (int o = 16; o; o >>= 1) s += __shfl_xor_sync(0xffffffffu, s, o);
        float lv = -INFINITY;
        if (lane == lab)           lv = v0;
        else if (lane + 32 == lab) lv = v1;
        else if (lane + 64 == lab) lv = v2;
        #pragma unroll
        for (int o = 16; o; o >>= 1) lv = fmaxf(lv, __shfl_xor_sync(0xffffffffu, lv, o));
        cls_acc += (m + logf(s)) - lv;

        if (lab > 0) {
            float sl = 0.f;
            if (lane < 4) {
                float d  = br[(size_t)row * (C_CLS * 4) + lab * 4 + lane] - tgt[row * 4 + lane];
                float ad = fabsf(d);
                sl = (ad < BETA) ? 0.5f * d * d / BETA : ad - 0.5f * BETA;
            }
            sl += __shfl_xor_sync(0xffffffffu, sl, 1);
            sl += __shfl_xor_sync(0xffffffffu, sl, 2);
            if (lane == 0) box_acc += sl;
        }
    }

    __shared__ float scls[8], sbox[8];
    int wid = threadIdx.x >> 5;
    if (lane == 0) { scls[wid] = cls_acc; sbox[wid] = box_acc; }
    __syncthreads();
    if (threadIdx.x == 0) {
        float c = 0.f, b = 0.f;
        #pragma unroll
        for (int i = 0; i < 8; i++) { c += scls[i]; b += sbox[i]; }
        g_partials[blockIdx.x * 2]     = c;
        g_partials[blockIdx.x * 2 + 1] = b;
    }
}

__global__ void loss_final_kernel(float* __restrict__ out)
{
    if (threadIdx.x == 0) {
        float c = 0.f, b = 0.f;
        for (int i = 0; i < LOSS_BLOCKS; i++) { c += g_partials[2*i]; b += g_partials[2*i+1]; }
        out[0] = c / (float)N_ROWS;
        out[1] = b / (float)N_ROWS;
    }
}

// ---------------------------------------------------------------------------
extern "C" void kernel_launch(void* const* d_in, const int* in_sizes, int n_in,
                              void* d_out, int out_size)
{
    const float* class_logits       = (const float*)d_in[0];
    const float* box_regression     = (const float*)d_in[1];
    const int*   labels             = (const int*)  d_in[2];
    const float* regression_targets = (const float*)d_in[3];
    const float* kp_maps            = (const float*)d_in[4];
    const float* kp_rois            = (const float*)d_in[5];
    const float* mask_logits        = (const float*)d_in[6];
    const int*   mask_labels        = (const int*)  d_in[7];
    float* out = (float*)d_out;

    kp_kernel<<<R_ROI * K_KP, 256>>>(kp_maps, kp_rois, out);
    mask_kernel<<<(R_ROI * MASK_HW + 255) / 256, 256>>>(mask_logits, mask_labels, out);
    loss_partial_kernel<<<LOSS_BLOCKS, 256>>>(class_logits, box_regression, labels,
                                              regression_targets);
    loss_final_kernel<<<1, 32>>>(out);
}

// round 3
// speedup vs baseline: 1.2227x; 1.2227x over previous
#include <cuda_runtime.h>
#include <math.h>

#define N_ROWS 4096
#define C_CLS  91
#define R_ROI  1024
#define K_KP   17
#define HM     56
#define RESO   64
#define BETA   (1.0f/9.0f)

#define OFF_XY   2
#define OFF_ES   (2 + R_ROI*K_KP*3)            /* 52226 */
#define OFF_MASK (OFF_ES + R_ROI*K_KP)         /* 69634 */
#define MASK_HW  784

#define KP_BLOCKS   (R_ROI * K_KP)             /* 17408 */
#define MASK_F2     (R_ROI * MASK_HW / 2)      /* 401408 float2 */
#define MASK_BLOCKS (MASK_F2 / 256)            /* 1568 */
#define LOSS_BLOCKS 64
#define TOTAL_BLOCKS (KP_BLOCKS + MASK_BLOCKS + LOSS_BLOCKS)

#define TMPW 65                                 /* padded row width */

__device__ float g_partials[2 * LOSS_BLOCKS];

// ---------------------------------------------------------------------------
// Keypoint block: bicubic 56->64 (jax semantics) + argmax. Issue-count
// optimized: one register weight-vector per thread serves BOTH dims.
// ---------------------------------------------------------------------------
__device__ __forceinline__ void kp_block(
    int map_id, const float* __restrict__ maps, const float* __restrict__ rois,
    float* __restrict__ out)
{
    __shared__ float  smap[HM * HM];          // 12544 B
    __shared__ float  stmp[HM * TMPW];        // 14560 B
    __shared__ float4 sw4[RESO];
    __shared__ int    sbase[RESO];
    __shared__ float  swv[8];
    __shared__ int    swi[8];

    const int tid = threadIdx.x;

    // Build weight table once (identical for x and y: 56->64 both dims).
    // Combined-slot form: base clamped to [0,52]; OOB taps get weight 0 at
    // their clamped slot; remaining weights renormalized (jax resize).
    if (tid < RESO) {
        float s = (tid + 0.5f) * ((float)HM / (float)RESO) - 0.5f;
        int b = (int)floorf(s);
        int base = min(max(b - 1, 0), HM - 4);
        float w[4] = {0.f, 0.f, 0.f, 0.f};
        float wsum = 0.f;
        #pragma unroll
        for (int j = 0; j < 4; j++) {
            int k = b - 1 + j;
            float t = fabsf(s - (float)k);
            float wc = (t < 1.f) ? ((1.5f*t - 2.5f)*t)*t + 1.f
                                 : ((-0.5f*t + 2.5f)*t - 4.f)*t + 2.f;
            if (k >= 0 && k < HM) { w[k - base] = wc; wsum += wc; }
        }
        float inv = 1.f / wsum;
        sw4[tid]   = make_float4(w[0]*inv, w[1]*inv, w[2]*inv, w[3]*inv);
        sbase[tid] = base;
    }

    // Stage map into smem, float4 (12544 B is 16B-aligned per map).
    {
        const float4* mp4 = (const float4*)(maps + (size_t)map_id * (HM * HM));
        float4* sm4 = (float4*)smap;
        #pragma unroll
        for (int i = 0; i < 4; i++) {
            int idx = tid + i * 256;
            if (idx < (HM * HM / 4)) sm4[idx] = __ldg(&mp4[idx]);
        }
    }
    __syncthreads();

    const int lane_o = tid & 63;   // xo in stage1, yo in stage2
    const int g      = tid >> 6;   // 0..3
    const float4 w   = sw4[lane_o];
    const int   base = sbase[lane_o];

    // Stage 1: x-interp. Thread owns column xo=lane_o; rows y = g,g+4,...
    #pragma unroll
    for (int i = 0; i < HM / 4; i++) {
        int y = g + i * 4;
        const float* rp = smap + y * HM + base;
        float acc = fmaf(w.x, rp[0], fmaf(w.y, rp[1], fmaf(w.z, rp[2], w.w * rp[3])));
        stmp[y * TMPW + lane_o] = acc;
    }
    __syncthreads();

    // Stage 2: y-interp + fused argmax. Thread owns row yo=lane_o; cols
    // xo = g*16 .. g*16+15 (p increases within thread -> first-index ties).
    float best = -INFINITY; int bidx = 0;
    const float* cbase = stmp + base * TMPW + g * 16;
    #pragma unroll
    for (int i = 0; i < 16; i++) {
        const float* cp = cbase + i;
        float acc = fmaf(w.x, cp[0], fmaf(w.y, cp[TMPW],
                    fmaf(w.z, cp[2*TMPW], w.w * cp[3*TMPW])));
        int p = (lane_o << 6) | (g * 16 + i);
        if (acc > best) { best = acc; bidx = p; }
    }

    // Warp shuffle reduction (value desc, index asc on ties).
    #pragma unroll
    for (int o = 16; o; o >>= 1) {
        float ov = __shfl_xor_sync(0xffffffffu, best, o);
        int   oi = __shfl_xor_sync(0xffffffffu, bidx, o);
        if (ov > best || (ov == best && oi < bidx)) { best = ov; bidx = oi; }
    }
    if ((tid & 31) == 0) { swv[tid >> 5] = best; swi[tid >> 5] = bidx; }
    __syncthreads();

    if (tid == 0) {
        #pragma unroll
        for (int i = 1; i < 8; i++) {
            if (swv[i] > best || (swv[i] == best && swi[i] < bidx)) {
                best = swv[i]; bidx = swi[i];
            }
        }
        int r = map_id / K_KP;
        float4 rb = __ldg((const float4*)(rois + r * 4));
        float wc = fmaxf(rb.z - rb.x, 1.f) * (1.f / (float)RESO);
        float hc = fmaxf(rb.w - rb.y, 1.f) * (1.f / (float)RESO);
        int xi = bidx & 63, yi = bidx >> 6;
        float* xy = out + OFF_XY + (size_t)map_id * 3;
        xy[0] = (xi + 0.5f) * wc + rb.x;
        xy[1] = (yi + 0.5f) * hc + rb.y;
        xy[2] = 1.f;
        out[OFF_ES + map_id] = best;
    }
}

// ---------------------------------------------------------------------------
// Mask inference block: gather selected class plane + sigmoid, float2 path.
// ---------------------------------------------------------------------------
__device__ __forceinline__ void mask_block(
    int mb, const float* __restrict__ mlog, const int* __restrict__ mlab,
    float* __restrict__ out)
{
    int idx = mb * 256 + threadIdx.x;          // float2 index < MASK_F2
    int r = idx / (MASK_HW / 2);
    int i = idx - r * (MASK_HW / 2);
    int lab = __ldg(&mlab[r]);
    float2 v = __ldg((const float2*)mlog + ((size_t)r * C_CLS + lab) * (MASK_HW / 2) + i);
    float2 o;
    o.x = 1.f / (1.f + expf(-v.x));
    o.y = 1.f / (1.f + expf(-v.y));
    ((float2*)(out + OFF_MASK))[idx] = o;
}

// ---------------------------------------------------------------------------
// FastRCNN loss partial block: warp-per-row logsumexp + smooth-L1 gather.
// ---------------------------------------------------------------------------
__device__ __forceinline__ void loss_block(
    int lb, const float* __restrict__ logits, const float* __restrict__ br,
    const int* __restrict__ labels, const float* __restrict__ tgt)
{
    __shared__ float scls[8], sbox[8];
    int lane  = threadIdx.x & 31;
    int wid   = threadIdx.x >> 5;
    int gwarp = lb * 8 + wid;
    const int nwarps = LOSS_BLOCKS * 8;

    float cls_acc = 0.f, box_acc = 0.f;
    for (int row = gwarp; row < N_ROWS; row += nwarps) {
        const float* lp = logits + (size_t)row * C_CLS;
        int lab = labels[row];
        float v0 = (lane      < C_CLS) ? lp[lane]      : -INFINITY;
        float v1 = (lane + 32 < C_CLS) ? lp[lane + 32] : -INFINITY;
        float v2 = (lane + 64 < C_CLS) ? lp[lane + 64] : -INFINITY;
        float m = fmaxf(v0, fmaxf(v1, v2));
        #pragma unroll
        for (int o = 16; o; o >>= 1) m = fmaxf(m, __shfl_xor_sync(0xffffffffu, m, o));
        float s = 0.f;
        if (lane      < C_CLS) s += expf(v0 - m);
        if (lane + 32 < C_CLS) s += expf(v1 - m);
        if (lane + 64 < C_CLS) s += expf(v2 - m);
        #pragma unroll
        for (int o = 16; o; o >>= 1) s += __shfl_xor_sync(0xffffffffu, s, o);
        float lv = -INFINITY;
        if (lane == lab)           lv = v0;
        else if (lane + 32 == lab) lv = v1;
        else if (lane + 64 == lab) lv = v2;
        #pragma unroll
        for (int o = 16; o; o >>= 1) lv = fmaxf(lv, __shfl_xor_sync(0xffffffffu, lv, o));
        cls_acc += (m + logf(s)) - lv;

        if (lab > 0) {
            float sl = 0.f;
            if (lane < 4) {
                float d  = br[(size_t)row * (C_CLS * 4) + lab * 4 + lane] - tgt[row * 4 + lane];
                float ad = fabsf(d);
                sl = (ad < BETA) ? 0.5f * d * d / BETA : ad - 0.5f * BETA;
            }
            sl += __shfl_xor_sync(0xffffffffu, sl, 1);
            sl += __shfl_xor_sync(0xffffffffu, sl, 2);
            if (lane == 0) box_acc += sl;
        }
    }

    if (lane == 0) { scls[wid] = cls_acc; sbox[wid] = box_acc; }
    __syncthreads();
    if (threadIdx.x == 0) {
        float c = 0.f, b = 0.f;
        #pragma unroll
        for (int i = 0; i < 8; i++) { c += scls[i]; b += sbox[i]; }
        g_partials[lb * 2]     = c;
        g_partials[lb * 2 + 1] = b;
    }
}

// ---------------------------------------------------------------------------
// Fused kernel: block-ID dispatch. kp blocks first (longest-running).
// ---------------------------------------------------------------------------
__global__ void __launch_bounds__(256) fused_kernel(
    const float* __restrict__ logits, const float* __restrict__ br,
    const int*   __restrict__ labels, const float* __restrict__ tgt,
    const float* __restrict__ kp_maps, const float* __restrict__ kp_rois,
    const float* __restrict__ mlog, const int* __restrict__ mlab,
    float* __restrict__ out)
{
    int b = blockIdx.x;
    if (b < KP_BLOCKS) {
        kp_block(b, kp_maps, kp_rois, out);
    } else if (b < KP_BLOCKS + MASK_BLOCKS) {
        mask_block(b - KP_BLOCKS, mlog, mlab, out);
    } else {
        loss_block(b - (KP_BLOCKS + MASK_BLOCKS), logits, br, labels, tgt);
    }
}

// ---------------------------------------------------------------------------
// Final reduction: one warp, deterministic shuffle reduce over 64 partials.
// ---------------------------------------------------------------------------
__global__ void loss_final_kernel(float* __restrict__ out)
{
    int lane = threadIdx.x;
    float c = 0.f, b = 0.f;
    for (int i = lane; i < LOSS_BLOCKS; i += 32) {
        c += g_partials[2 * i];
        b += g_partials[2 * i + 1];
    }
    #pragma unroll
    for (int o = 16; o; o >>= 1) {
        c += __shfl_xor_sync(0xffffffffu, c, o);
        b += __shfl_xor_sync(0xffffffffu, b, o);
    }
    if (lane == 0) {
        out[0] = c * (1.f / (float)N_ROWS);
        out[1] = b * (1.f / (float)N_ROWS);
    }
}

// ---------------------------------------------------------------------------
extern "C" void kernel_launch(void* const* d_in, const int* in_sizes, int n_in,
                              void* d_out, int out_size)
{
    const float* class_logits       = (const float*)d_in[0];
    const float* box_regression     = (const float*)d_in[1];
    const int*   labels             = (const int*)  d_in[2];
    const float* regression_targets = (const float*)d_in[3];
    const float* kp_maps            = (const float*)d_in[4];
    const float* kp_rois            = (const float*)d_in[5];
    const float* mask_logits        = (const float*)d_in[6];
    const int*   mask_labels        = (const int*)  d_in[7];
    float* out = (float*)d_out;

    fused_kernel<<<TOTAL_BLOCKS, 256>>>(class_logits, box_regression, labels,
                                        regression_targets, kp_maps, kp_rois,
                                        mask_logits, mask_labels, out);
    loss_final_kernel<<<1, 32>>>(out);
}

// round 6
// speedup vs baseline: 1.9700x; 1.6113x over previous
#include <cuda_runtime.h>
#include <math.h>

#define N_ROWS 4096
#define C_CLS  91
#define R_ROI  1024
#define K_KP   17
#define HM     56
#define RESO   64
#define BETA   (1.0f/9.0f)

#define OFF_XY   2
#define OFF_ES   (2 + R_ROI*K_KP*3)            /* 52226 */
#define OFF_MASK (OFF_ES + R_ROI*K_KP)         /* 69634 */
#define MASK_HW  784

#define KP_BLOCKS   (R_ROI * K_KP)             /* 17408 */
#define MASK_F2     (R_ROI * MASK_HW / 2)      /* 401408 */
#define MASK_BLOCKS (MASK_F2 / 256)            /* 1568 */
#define LOSS_BLOCKS 64
#define TOTAL_BLOCKS (KP_BLOCKS + MASK_BLOCKS + LOSS_BLOCKS)

#define SROW 60                                 /* padded row stride (floats) */

__device__ float g_partials[2 * LOSS_BLOCKS];
__device__ int   g_done = 0;

// ---------------------------------------------------------------------------
// Window parameters for the 56->64 bicubic resample, computed constexpr.
// s(xo) = (14*xo - 1)/16 exactly; base(xo) = clamp(floor(s)-1, 0, 52).
// Quarter Q covers xo = 16Q..16Q+15; W(Q) = aligned window start,
// NL(Q) = #float4 loads, S(Q,j) = base(16Q+j) - W(Q).
// ---------------------------------------------------------------------------
__host__ __device__ constexpr int qp_base(int xo) {
    int num = 14 * xo - 1;                                   // s = num/16
    int fl  = (num >= 0) ? (num / 16) : -((-num + 15) / 16); // floor(s)
    int b   = fl - 1;
    return (b < 0) ? 0 : ((b > HM - 4) ? (HM - 4) : b);
}
__host__ __device__ constexpr int qp_W(int Q)  { return Q==0?0 : Q==1?12 : Q==2?24 : 40; }
__host__ __device__ constexpr int qp_NL(int Q) { return (Q==1 || Q==2) ? 5 : 4; }
__host__ __device__ constexpr int qp_S(int Q, int j) { return qp_base(16*Q + j) - qp_W(Q); }

// Interpolate 16 consecutive outputs (xo = 16Q..16Q+15) of one line.
// row: 56-float line (stride 1), 16B-aligned at W(Q) offsets.
// wt: combined-slot weight table in smem. emit(j, v) consumes output j.
template<int Q, typename F>
__device__ __forceinline__ void interp16(const float* __restrict__ row,
                                         const float4* __restrict__ wt,
                                         F emit)
{
    float4 win4[qp_NL(Q)];                       // 16B-aligned by type
    #pragma unroll
    for (int i = 0; i < qp_NL(Q); i++)
        win4[i] = *(const float4*)(row + qp_W(Q) + 4*i);
    const float* win = (const float*)win4;
    #pragma unroll
    for (int j = 0; j < 16; j++) {
        const int s = qp_S(Q, j);                // compile-time constant
        float4 w = wt[16*Q + j];                 // warp-broadcast LDS.128
        float v = fmaf(w.x, win[s],
                  fmaf(w.y, win[s+1],
                  fmaf(w.z, win[s+2], w.w * win[s+3])));
        emit(j, v);
    }
}

// ---------------------------------------------------------------------------
// Keypoint block: bicubic 56->64 (jax semantics) + argmax, register
// sliding-window both stages, transposed intermediate.
// ---------------------------------------------------------------------------
__device__ __forceinline__ void kp_block(
    int map_id, const float* __restrict__ maps, const float* __restrict__ rois,
    float* __restrict__ out)
{
    __shared__ __align__(16) float smap[HM * SROW];   // 13440 B (padded rows)
    __shared__ __align__(16) float tmpT[RESO * SROW]; // 15360 B ([xo][y])
    __shared__ float4 sw4[RESO];
    __shared__ float  swv[8];
    __shared__ int    swi[8];

    const int tid = threadIdx.x;

    // Weight table (combined-slot, renormalized at boundaries — jax resize).
    if (tid < RESO) {
        float s = (tid + 0.5f) * ((float)HM / (float)RESO) - 0.5f;
        int b = (int)floorf(s);
        int base = min(max(b - 1, 0), HM - 4);
        float w[4] = {0.f, 0.f, 0.f, 0.f};
        float wsum = 0.f;
        #pragma unroll
        for (int j = 0; j < 4; j++) {
            int k = b - 1 + j;
            float t = fabsf(s - (float)k);
            float wc = (t < 1.f) ? ((1.5f*t - 2.5f)*t)*t + 1.f
                                 : ((-0.5f*t + 2.5f)*t - 4.f)*t + 2.f;
            if (k >= 0 && k < HM) { w[k - base] = wc; wsum += wc; }
        }
        float inv = 1.f / wsum;
        sw4[tid] = make_float4(w[0]*inv, w[1]*inv, w[2]*inv, w[3]*inv);
    }

    // Stage map into padded smem rows (float4; 56 % 4 == 0, never row-cross;
    // per-map byte offset 12544 is 16B-multiple, row stride 240B likewise).
    {
        const float4* mp4 = (const float4*)(maps + (size_t)map_id * (HM * HM));
        #pragma unroll
        for (int i = 0; i < 4; i++) {
            int idx = tid + i * 256;
            if (idx < (HM * HM / 4)) {
                float4 v = __ldg(&mp4[idx]);
                int y = idx / 14, c = idx - y * 14;
                *(float4*)(smap + y * SROW + 4*c) = v;
            }
        }
    }
    __syncthreads();

    const int lane_o = tid & 63;
    const int q      = tid >> 6;              // warp-uniform

    // Stage 1: x-interp. Thread: row y=lane_o (<56), outputs xo=16q..16q+15,
    // written transposed: tmpT[xo*SROW + y].
    if (lane_o < HM) {
        const float* row = smap + lane_o * SROW;
        float* tc = tmpT + lane_o;
        switch (q) {
        case 0: interp16<0>(row, sw4, [&](int j, float v){ tc[(   j)*SROW] = v; }); break;
        case 1: interp16<1>(row, sw4, [&](int j, float v){ tc[(16+j)*SROW] = v; }); break;
        case 2: interp16<2>(row, sw4, [&](int j, float v){ tc[(32+j)*SROW] = v; }); break;
        default:interp16<3>(row, sw4, [&](int j, float v){ tc[(48+j)*SROW] = v; }); break;
        }
    }
    __syncthreads();

    // Stage 2: y-interp + fused argmax. Thread: column xo=lane_o, outputs
    // yo=16q..16q+15. p = yo*64+xo ascends within thread -> first-index ties.
    float best = -INFINITY; int bidx = 0;
    {
        const float* row = tmpT + lane_o * SROW;   // 56 y-values for this xo
        const int xo = lane_o;
        switch (q) {
        case 0: interp16<0>(row, sw4, [&](int j, float v){
                    int p = ((   j) << 6) | xo;
                    if (v > best) { best = v; bidx = p; } }); break;
        case 1: interp16<1>(row, sw4, [&](int j, float v){
                    int p = ((16+j) << 6) | xo;
                    if (v > best) { best = v; bidx = p; } }); break;
        case 2: interp16<2>(row, sw4, [&](int j, float v){
                    int p = ((32+j) << 6) | xo;
                    if (v > best) { best = v; bidx = p; } }); break;
        default:interp16<3>(row, sw4, [&](int j, float v){
                    int p = ((48+j) << 6) | xo;
                    if (v > best) { best = v; bidx = p; } }); break;
        }
    }

    #pragma unroll
    for (int o = 16; o; o >>= 1) {
        float ov = __shfl_xor_sync(0xffffffffu, best, o);
        int   oi = __shfl_xor_sync(0xffffffffu, bidx, o);
        if (ov > best || (ov == best && oi < bidx)) { best = ov; bidx = oi; }
    }
    if ((tid & 31) == 0) { swv[tid >> 5] = best; swi[tid >> 5] = bidx; }
    __syncthreads();

    if (tid == 0) {
        #pragma unroll
        for (int i = 1; i < 8; i++) {
            if (swv[i] > best || (swv[i] == best && swi[i] < bidx)) {
                best = swv[i]; bidx = swi[i];
            }
        }
        int r = map_id / K_KP;
        const float* rp = rois + r * 4;           // scalar loads: no align req
        float x1 = rp[0], y1 = rp[1], x2 = rp[2], y2 = rp[3];
        float wc = fmaxf(x2 - x1, 1.f) * (1.f / (float)RESO);
        float hc = fmaxf(y2 - y1, 1.f) * (1.f / (float)RESO);
        int xi = bidx & 63, yi = bidx >> 6;
        float* xy = out + OFF_XY + (size_t)map_id * 3;
        xy[0] = (xi + 0.5f) * wc + x1;
        xy[1] = (yi + 0.5f) * hc + y1;
        xy[2] = 1.f;
        out[OFF_ES + map_id] = best;
    }
}

// ---------------------------------------------------------------------------
// Mask inference block: gather selected class plane + sigmoid (float2 path;
// all float2 offsets are 8B multiples: plane stride 3136B, OFF_MASK*4=278536).
// ---------------------------------------------------------------------------
__device__ __forceinline__ void mask_block(
    int mb, const float* __restrict__ mlog, const int* __restrict__ mlab,
    float* __restrict__ out)
{
    int idx = mb * 256 + threadIdx.x;
    int r = idx / (MASK_HW / 2);
    int i = idx - r * (MASK_HW / 2);
    int lab = __ldg(&mlab[r]);
    float2 v = __ldg((const float2*)mlog + ((size_t)r * C_CLS + lab) * (MASK_HW / 2) + i);
    float2 o;
    o.x = 1.f / (1.f + expf(-v.x));
    o.y = 1.f / (1.f + expf(-v.y));
    ((float2*)(out + OFF_MASK))[idx] = o;
}

// ---------------------------------------------------------------------------
// FastRCNN loss partial block + last-block final reduction (deterministic:
// fixed-order sums; atomic counter only selects WHICH block finishes).
// ---------------------------------------------------------------------------
__device__ __forceinline__ void loss_block(
    int lb, const float* __restrict__ logits, const float* __restrict__ br,
    const int* __restrict__ labels, const float* __restrict__ tgt,
    float* __restrict__ out)
{
    __shared__ float scls[8], sbox[8];
    __shared__ int   is_last;
    int lane  = threadIdx.x & 31;
    int wid   = threadIdx.x >> 5;
    int gwarp = lb * 8 + wid;
    const int nwarps = LOSS_BLOCKS * 8;

    float cls_acc = 0.f, box_acc = 0.f;
    for (int row = gwarp; row < N_ROWS; row += nwarps) {
        const float* lp = logits + (size_t)row * C_CLS;
        int lab = labels[row];
        float v0 = (lane      < C_CLS) ? lp[lane]      : -INFINITY;
        float v1 = (lane + 32 < C_CLS) ? lp[lane + 32] : -INFINITY;
        float v2 = (lane + 64 < C_CLS) ? lp[lane + 64] : -INFINITY;
        float m = fmaxf(v0, fmaxf(v1, v2));
        #pragma unroll
        for (int o = 16; o; o >>= 1) m = fmaxf(m, __shfl_xor_sync(0xffffffffu, m, o));
        float s = 0.f;
        if (lane      < C_CLS) s += expf(v0 - m);
        if (lane + 32 < C_CLS) s += expf(v1 - m);
        if (lane + 64 < C_CLS) s += expf(v2 - m);
        #pragma unroll
        for (int o = 16; o; o >>= 1) s += __shfl_xor_sync(0xffffffffu, s, o);
        float lv = -INFINITY;
        if (lane == lab)           lv = v0;
        else if (lane + 32 == lab) lv = v1;
        else if (lane + 64 == lab) lv = v2;
        #pragma unroll
        for (int o = 16; o; o >>= 1) lv = fmaxf(lv, __shfl_xor_sync(0xffffffffu, lv, o));
        cls_acc += (m + logf(s)) - lv;

        if (lab > 0) {
            float sl = 0.f;
            if (lane < 4) {
                float d  = br[(size_t)row * (C_CLS * 4) + lab * 4 + lane] - tgt[row * 4 + lane];
                float ad = fabsf(d);
                sl = (ad < BETA) ? 0.5f * d * d / BETA : ad - 0.5f * BETA;
            }
            sl += __shfl_xor_sync(0xffffffffu, sl, 1);
            sl += __shfl_xor_sync(0xffffffffu, sl, 2);
            if (lane == 0) box_acc += sl;
        }
    }

    if (lane == 0) { scls[wid] = cls_acc; sbox[wid] = box_acc; }
    __syncthreads();
    if (threadIdx.x == 0) {
        float c = 0.f, b = 0.f;
        #pragma unroll
        for (int i = 0; i < 8; i++) { c += scls[i]; b += sbox[i]; }
        g_partials[lb * 2]     = c;
        g_partials[lb * 2 + 1] = b;
        __threadfence();
        is_last = (atomicAdd(&g_done, 1) == LOSS_BLOCKS - 1);
    }
    __syncthreads();

    if (is_last && threadIdx.x < 32) {
        __threadfence();
        float c = 0.f, b = 0.f;
        for (int i = lane; i < LOSS_BLOCKS; i += 32) {
            c += g_partials[2 * i];
            b += g_partials[2 * i + 1];
        }
        #pragma unroll
        for (int o = 16; o; o >>= 1) {
            c += __shfl_xor_sync(0xffffffffu, c, o);
            b += __shfl_xor_sync(0xffffffffu, b, o);
        }
        if (lane == 0) {
            out[0] = c * (1.f / (float)N_ROWS);
            out[1] = b * (1.f / (float)N_ROWS);
            g_done = 0;                       // reset for next graph replay
        }
    }
}

// ---------------------------------------------------------------------------
__global__ void __launch_bounds__(256) fused_kernel(
    const float* __restrict__ logits, const float* __restrict__ br,
    const int*   __restrict__ labels, const float* __restrict__ tgt,
    const float* __restrict__ kp_maps, const float* __restrict__ kp_rois,
    const float* __restrict__ mlog, const int* __restrict__ mlab,
    float* __restrict__ out)
{
    int b = blockIdx.x;
    if (b < KP_BLOCKS) {
        kp_block(b, kp_maps, kp_rois, out);
    } else if (b < KP_BLOCKS + MASK_BLOCKS) {
        mask_block(b - KP_BLOCKS, mlog, mlab, out);
    } else {
        loss_block(b - (KP_BLOCKS + MASK_BLOCKS), logits, br, labels, tgt, out);
    }
}

// ---------------------------------------------------------------------------
extern "C" void kernel_launch(void* const* d_in, const int* in_sizes, int n_in,
                              void* d_out, int out_size)
{
    const float* class_logits       = (const float*)d_in[0];
    const float* box_regression     = (const float*)d_in[1];
    const int*   labels             = (const int*)  d_in[2];
    const float* regression_targets = (const float*)d_in[3];
    const float* kp_maps            = (const float*)d_in[4];
    const float* kp_rois            = (const float*)d_in[5];
    const float* mask_logits        = (const float*)d_in[6];
    const int*   mask_labels        = (const int*)  d_in[7];
    float* out = (float*)d_out;

    fused_kernel<<<TOTAL_BLOCKS, 256>>>(class_logits, box_regression, labels,
                                        regression_targets, kp_maps, kp_rois,
                                        mask_logits, mask_labels, out);
}

// round 7
// speedup vs baseline: 2.6599x; 1.3502x over previous
#include <cuda_runtime.h>
#include <math.h>

#define N_ROWS 4096
#define C_CLS  91
#define R_ROI  1024
#define K_KP   17
#define HM     56
#define RESO   64
#define BETA   (1.0f/9.0f)

#define OFF_XY   2
#define OFF_ES   (2 + R_ROI*K_KP*3)            /* 52226 */
#define OFF_MASK (OFF_ES + R_ROI*K_KP)         /* 69634 */
#define MASK_HW  784

#define KP_BLOCKS   (R_ROI * K_KP)             /* 17408 */
#define MASK_F2     (R_ROI * MASK_HW / 2)      /* 401408 */
#define MASK_BLOCKS (MASK_F2 / 256)            /* 1568 */
#define LOSS_BLOCKS 64
#define TOTAL_BLOCKS (KP_BLOCKS + MASK_BLOCKS + LOSS_BLOCKS)

#define SROW 60                                 /* padded row stride (floats) */

__device__ float g_partials[2 * LOSS_BLOCKS];
__device__ int   g_done = 0;

// ---------------------------------------------------------------------------
// Compile-time bicubic 56->64 resample parameters (jax.image.resize
// semantics: half-pixel sampling, Keys a=-0.5, OOB taps dropped + renorm).
// s(xo) = (14*xo - 1)/16 exactly.
// ---------------------------------------------------------------------------
__host__ __device__ constexpr int qp_floor(int xo) {
    int num = 14 * xo - 1;
    return (num >= 0) ? num / 16 : -((-num + 15) / 16);
}
__host__ __device__ constexpr int qp_base(int xo) {
    int b = qp_floor(xo) - 1;
    return (b < 0) ? 0 : ((b > HM - 4) ? (HM - 4) : b);
}
__host__ __device__ constexpr int qp_W(int Q)  { return Q==0?0 : Q==1?12 : Q==2?24 : 40; }
__host__ __device__ constexpr int qp_NL(int Q) { return (Q==1 || Q==2) ? 5 : 4; }
__host__ __device__ constexpr int qp_S(int Q, int j) { return qp_base(16*Q + j) - qp_W(Q); }

__host__ __device__ constexpr float qp_cubic(int dn16) {   // t = |dn16|/16
    float t = (float)(dn16 < 0 ? -dn16 : dn16) / 16.0f;
    return (t < 1.0f) ? ((1.5f*t - 2.5f)*t)*t + 1.0f
         : (t < 2.0f) ? ((-0.5f*t + 2.5f)*t - 4.0f)*t + 2.0f
         : 0.0f;
}
__host__ __device__ constexpr float qp_wsum(int xo) {
    float s = 0.f;
    for (int k = qp_floor(xo) - 1; k <= qp_floor(xo) + 2; ++k)
        if (k >= 0 && k < HM) s += qp_cubic(14*xo - 1 - 16*k);
    return s;
}
__host__ __device__ constexpr float qp_wt(int xo, int slot) {
    int k = qp_base(xo) + slot;
    if (k < qp_floor(xo) - 1 || k > qp_floor(xo) + 2 || k < 0 || k >= HM)
        return 0.0f;
    return qp_cubic(14*xo - 1 - 16*k) * (1.0f / qp_wsum(xo));
}

// C++11-safe compile-time for: f(integral_constant<int,J>) for J=0..N-1.
template<int J, int N> struct SFor {
    template<typename F> __device__ __forceinline__ static void run(F&& f) {
        f(J_tag()); SFor<J+1, N>::run(f);
    }
    struct J_tag { static constexpr int value = J; };
};
template<int N> struct SFor<N, N> {
    template<typename F> __device__ __forceinline__ static void run(F&&) {}
};

// Interpolate 16 consecutive outputs (xo = 16Q..16Q+15) of one line.
// All weights are FFMA immediates; zero weights fold away at the boundary.
template<int Q, typename F>
__device__ __forceinline__ void interp16(const float* __restrict__ row, F emit)
{
    float4 win4[qp_NL(Q)];                       // 16B-aligned by type
    #pragma unroll
    for (int i = 0; i < qp_NL(Q); i++)
        win4[i] = *(const float4*)(row + qp_W(Q) + 4*i);
    const float* win = (const float*)win4;
    SFor<0, 16>::run([&](auto jc) {
        constexpr int   j  = decltype(jc)::value;
        constexpr int   s  = qp_S(Q, j);
        constexpr int   xo = 16*Q + j;
        constexpr float w0 = qp_wt(xo, 0), w1 = qp_wt(xo, 1);
        constexpr float w2 = qp_wt(xo, 2), w3 = qp_wt(xo, 3);
        float v = fmaf(w0, win[s],
                  fmaf(w1, win[s+1],
                  fmaf(w2, win[s+2], w3 * win[s+3])));
        emit(j, v);
    });
}

// ---------------------------------------------------------------------------
// Keypoint block: bicubic 56->64 + argmax, register sliding-window both
// stages, transposed intermediate, immediate-constant weights.
// ---------------------------------------------------------------------------
__device__ __forceinline__ void kp_block(
    int map_id, const float* __restrict__ maps, const float* __restrict__ rois,
    float* __restrict__ out)
{
    __shared__ __align__(16) float smap[HM * SROW];   // 13440 B (padded rows)
    __shared__ __align__(16) float tmpT[RESO * SROW]; // 15360 B ([xo][y])
    __shared__ float swv[8];
    __shared__ int   swi[8];

    const int tid = threadIdx.x;

    // Stage map into padded smem rows (float4; 56 % 4 == 0, never row-cross;
    // per-map byte offset 12544 and row stride 240B are 16B multiples).
    {
        const float4* mp4 = (const float4*)(maps + (size_t)map_id * (HM * HM));
        #pragma unroll
        for (int i = 0; i < 4; i++) {
            int idx = tid + i * 256;
            if (idx < (HM * HM / 4)) {
                float4 v = __ldg(&mp4[idx]);
                int y = idx / 14, c = idx - y * 14;
                *(float4*)(smap + y * SROW + 4*c) = v;
            }
        }
    }
    __syncthreads();

    const int lane_o = tid & 63;
    const int q      = tid >> 6;              // warp-uniform

    // Stage 1: x-interp. Thread: row y=lane_o (<56), outputs xo=16q..16q+15,
    // written transposed: tmpT[xo*SROW + y]. (stride-1 across warp -> no STS
    // conflicts; outputs of a warp share j.)
    if (lane_o < HM) {
        const float* row = smap + lane_o * SROW;
        float* tc = tmpT + lane_o;
        switch (q) {
        case 0: interp16<0>(row, [&](int j, float v){ tc[(   j)*SROW] = v; }); break;
        case 1: interp16<1>(row, [&](int j, float v){ tc[(16+j)*SROW] = v; }); break;
        case 2: interp16<2>(row, [&](int j, float v){ tc[(32+j)*SROW] = v; }); break;
        default:interp16<3>(row, [&](int j, float v){ tc[(48+j)*SROW] = v; }); break;
        }
    }
    __syncthreads();

    // Stage 2: y-interp + fused argmax. Thread: column xo=lane_o, outputs
    // yo=16q..16q+15. p = yo*64+xo ascends within thread -> first-index ties.
    float best = -INFINITY; int bidx = 0;
    {
        const float* row = tmpT + lane_o * SROW;   // 56 y-values for this xo
        const int xo = lane_o;
        switch (q) {
        case 0: interp16<0>(row, [&](int j, float v){
                    int p = ((   j) << 6) | xo;
                    if (v > best) { best = v; bidx = p; } }); break;
        case 1: interp16<1>(row, [&](int j, float v){
                    int p = ((16+j) << 6) | xo;
                    if (v > best) { best = v; bidx = p; } }); break;
        case 2: interp16<2>(row, [&](int j, float v){
                    int p = ((32+j) << 6) | xo;
                    if (v > best) { best = v; bidx = p; } }); break;
        default:interp16<3>(row, [&](int j, float v){
                    int p = ((48+j) << 6) | xo;
                    if (v > best) { best = v; bidx = p; } }); break;
        }
    }

    #pragma unroll
    for (int o = 16; o; o >>= 1) {
        float ov = __shfl_xor_sync(0xffffffffu, best, o);
        int   oi = __shfl_xor_sync(0xffffffffu, bidx, o);
        if (ov > best || (ov == best && oi < bidx)) { best = ov; bidx = oi; }
    }
    if ((tid & 31) == 0) { swv[tid >> 5] = best; swi[tid >> 5] = bidx; }
    __syncthreads();

    if (tid == 0) {
        #pragma unroll
        for (int i = 1; i < 8; i++) {
            if (swv[i] > best || (swv[i] == best && swi[i] < bidx)) {
                best = swv[i]; bidx = swi[i];
            }
        }
        int r = map_id / K_KP;
        const float* rp = rois + r * 4;
        float x1 = rp[0], y1 = rp[1], x2 = rp[2], y2 = rp[3];
        float wc = fmaxf(x2 - x1, 1.f) * (1.f / (float)RESO);
        float hc = fmaxf(y2 - y1, 1.f) * (1.f / (float)RESO);
        int xi = bidx & 63, yi = bidx >> 6;
        float* xy = out + OFF_XY + (size_t)map_id * 3;
        xy[0] = (xi + 0.5f) * wc + x1;
        xy[1] = (yi + 0.5f) * hc + y1;
        xy[2] = 1.f;
        out[OFF_ES + map_id] = best;
    }
}

// ---------------------------------------------------------------------------
// Mask inference block: gather selected class plane + sigmoid (float2 path).
// ---------------------------------------------------------------------------
__device__ __forceinline__ void mask_block(
    int mb, const float* __restrict__ mlog, const int* __restrict__ mlab,
    float* __restrict__ out)
{
    int idx = mb * 256 + threadIdx.x;
    int r = idx / (MASK_HW / 2);
    int i = idx - r * (MASK_HW / 2);
    int lab = __ldg(&mlab[r]);
    float2 v = __ldg((const float2*)mlog + ((size_t)r * C_CLS + lab) * (MASK_HW / 2) + i);
    float2 o;
    o.x = 1.f / (1.f + expf(-v.x));
    o.y = 1.f / (1.f + expf(-v.y));
    ((float2*)(out + OFF_MASK))[idx] = o;
}

// ---------------------------------------------------------------------------
// FastRCNN loss partial block + last-block final reduction (deterministic:
// fixed-order sums; atomic counter only selects WHICH block finishes).
// ---------------------------------------------------------------------------
__device__ __forceinline__ void loss_block(
    int lb, const float* __restrict__ logits, const float* __restrict__ br,
    const int* __restrict__ labels, const float* __restrict__ tgt,
    float* __restrict__ out)
{
    __shared__ float scls[8], sbox[8];
    __shared__ int   is_last;
    int lane  = threadIdx.x & 31;
    int wid   = threadIdx.x >> 5;
    int gwarp = lb * 8 + wid;
    const int nwarps = LOSS_BLOCKS * 8;

    float cls_acc = 0.f, box_acc = 0.f;
    for (int row = gwarp; row < N_ROWS; row += nwarps) {
        const float* lp = logits + (size_t)row * C_CLS;
        int lab = labels[row];
        float v0 = (lane      < C_CLS) ? lp[lane]      : -INFINITY;
        float v1 = (lane + 32 < C_CLS) ? lp[lane + 32] : -INFINITY;
        float v2 = (lane + 64 < C_CLS) ? lp[lane + 64] : -INFINITY;
        float m = fmaxf(v0, fmaxf(v1, v2));
        #pragma unroll
        for (int o = 16; o; o >>= 1) m = fmaxf(m, __shfl_xor_sync(0xffffffffu, m, o));
        float s = 0.f;
        if (lane      < C_CLS) s += expf(v0 - m);
        if (lane + 32 < C_CLS) s += expf(v1 - m);
        if (lane + 64 < C_CLS) s += expf(v2 - m);
        #pragma unroll
        for (int o = 16; o; o >>= 1) s += __shfl_xor_sync(0xffffffffu, s, o);
        float lv = -INFINITY;
        if (lane == lab)           lv = v0;
        else if (lane + 32 == lab) lv = v1;
        else if (lane + 64 == lab) lv = v2;
        #pragma unroll
        for (int o = 16; o; o >>= 1) lv = fmaxf(lv, __shfl_xor_sync(0xffffffffu, lv, o));
        cls_acc += (m + logf(s)) - lv;

        if (lab > 0) {
            float sl = 0.f;
            if (lane < 4) {
                float d  = br[(size_t)row * (C_CLS * 4) + lab * 4 + lane] - tgt[row * 4 + lane];
                float ad = fabsf(d);
                sl = (ad < BETA) ? 0.5f * d * d / BETA : ad - 0.5f * BETA;
            }
            sl += __shfl_xor_sync(0xffffffffu, sl, 1);
            sl += __shfl_xor_sync(0xffffffffu, sl, 2);
            if (lane == 0) box_acc += sl;
        }
    }

    if (lane == 0) { scls[wid] = cls_acc; sbox[wid] = box_acc; }
    __syncthreads();
    if (threadIdx.x == 0) {
        float c = 0.f, b = 0.f;
        #pragma unroll
        for (int i = 0; i < 8; i++) { c += scls[i]; b += sbox[i]; }
        g_partials[lb * 2]     = c;
        g_partials[lb * 2 + 1] = b;
        __threadfence();
        is_last = (atomicAdd(&g_done, 1) == LOSS_BLOCKS - 1);
    }
    __syncthreads();

    if (is_last && threadIdx.x < 32) {
        __threadfence();
        float c = 0.f, b = 0.f;
        for (int i = lane; i < LOSS_BLOCKS; i += 32) {
            c += g_partials[2 * i];
            b += g_partials[2 * i + 1];
        }
        #pragma unroll
        for (int o = 16; o; o >>= 1) {
            c += __shfl_xor_sync(0xffffffffu, c, o);
            b += __shfl_xor_sync(0xffffffffu, b, o);
        }
        if (lane == 0) {
            out[0] = c * (1.f / (float)N_ROWS);
            out[1] = b * (1.f / (float)N_ROWS);
            g_done = 0;                       // reset for next graph replay
        }
    }
}

// ---------------------------------------------------------------------------
__global__ void __launch_bounds__(256) fused_kernel(
    const float* __restrict__ logits, const float* __restrict__ br,
    const int*   __restrict__ labels, const float* __restrict__ tgt,
    const float* __restrict__ kp_maps, const float* __restrict__ kp_rois,
    const float* __restrict__ mlog, const int* __restrict__ mlab,
    float* __restrict__ out)
{
    int b = blockIdx.x;
    if (b < KP_BLOCKS) {
        kp_block(b, kp_maps, kp_rois, out);
    } else if (b < KP_BLOCKS + MASK_BLOCKS) {
        mask_block(b - KP_BLOCKS, mlog, mlab, out);
    } else {
        loss_block(b - (KP_BLOCKS + MASK_BLOCKS), logits, br, labels, tgt, out);
    }
}

// ---------------------------------------------------------------------------
extern "C" void kernel_launch(void* const* d_in, const int* in_sizes, int n_in,
                              void* d_out, int out_size)
{
    const float* class_logits       = (const float*)d_in[0];
    const float* box_regression     = (const float*)d_in[1];
    const int*   labels             = (const int*)  d_in[2];
    const float* regression_targets = (const float*)d_in[3];
    const float* kp_maps            = (const float*)d_in[4];
    const float* kp_rois            = (const float*)d_in[5];
    const float* mask_logits        = (const float*)d_in[6];
    const int*   mask_labels        = (const int*)  d_in[7];
    float* out = (float*)d_out;

    fused_kernel<<<TOTAL_BLOCKS, 256>>>(class_logits, box_regression, labels,
                                        regression_targets, kp_maps, kp_rois,
                                        mask_logits, mask_labels, out);
}

// round 8
// speedup vs baseline: 3.2428x; 1.2191x over previous
#include <cuda_runtime.h>
#include <math.h>

#define N_ROWS 4096
#define C_CLS  91
#define R_ROI  1024
#define K_KP   17
#define HM     56
#define RESO   64
#define BETA   (1.0f/9.0f)

#define OFF_XY   2
#define OFF_ES   (2 + R_ROI*K_KP*3)            /* 52226 */
#define OFF_MASK (OFF_ES + R_ROI*K_KP)         /* 69634 */
#define MASK_HW  784

#define KP_BLOCKS   (R_ROI * K_KP)             /* 17408 */
#define MASK_F4     (R_ROI * MASK_HW / 4)      /* 200704 float4 loads */
#define MASK_BLOCKS (MASK_F4 / 256)            /* 784 */
#define LOSS_BLOCKS 64
#define TOTAL_BLOCKS (LOSS_BLOCKS + MASK_BLOCKS + KP_BLOCKS)

#define SROW 60                                 /* padded row stride (floats) */

__device__ float g_partials[2 * LOSS_BLOCKS];
__device__ int   g_done = 0;

// ---------------------------------------------------------------------------
// Compile-time bicubic 56->64 resample parameters (jax.image.resize
// semantics: half-pixel sampling, Keys a=-0.5, OOB taps dropped + renorm).
// s(xo) = (14*xo - 1)/16 exactly.
// ---------------------------------------------------------------------------
__host__ __device__ constexpr int qp_floor(int xo) {
    int num = 14 * xo - 1;
    return (num >= 0) ? num / 16 : -((-num + 15) / 16);
}
__host__ __device__ constexpr int qp_base(int xo) {
    int b = qp_floor(xo) - 1;
    return (b < 0) ? 0 : ((b > HM - 4) ? (HM - 4) : b);
}
__host__ __device__ constexpr int qp_W(int Q)  { return Q==0?0 : Q==1?12 : Q==2?24 : 40; }
__host__ __device__ constexpr int qp_NL(int Q) { return (Q==1 || Q==2) ? 5 : 4; }
__host__ __device__ constexpr int qp_S(int Q, int j) { return qp_base(16*Q + j) - qp_W(Q); }

__host__ __device__ constexpr float qp_cubic(int dn16) {   // t = |dn16|/16
    float t = (float)(dn16 < 0 ? -dn16 : dn16) / 16.0f;
    return (t < 1.0f) ? ((1.5f*t - 2.5f)*t)*t + 1.0f
         : (t < 2.0f) ? ((-0.5f*t + 2.5f)*t - 4.0f)*t + 2.0f
         : 0.0f;
}
__host__ __device__ constexpr float qp_wsum(int xo) {
    float s = 0.f;
    for (int k = qp_floor(xo) - 1; k <= qp_floor(xo) + 2; ++k)
        if (k >= 0 && k < HM) s += qp_cubic(14*xo - 1 - 16*k);
    return s;
}
__host__ __device__ constexpr float qp_wt(int xo, int slot) {
    int k = qp_base(xo) + slot;
    if (k < qp_floor(xo) - 1 || k > qp_floor(xo) + 2 || k < 0 || k >= HM)
        return 0.0f;
    return qp_cubic(14*xo - 1 - 16*k) * (1.0f / qp_wsum(xo));
}

// C++11-safe compile-time for.
template<int J, int N> struct SFor {
    template<typename F> __device__ __forceinline__ static void run(F&& f) {
        f(J_tag()); SFor<J+1, N>::run(f);
    }
    struct J_tag { static constexpr int value = J; };
};
template<int N> struct SFor<N, N> {
    template<typename F> __device__ __forceinline__ static void run(F&&) {}
};

// Interpolate 16 consecutive outputs (xo = 16Q..16Q+15) of one line.
// All weights are FFMA immediates.
template<int Q, typename F>
__device__ __forceinline__ void interp16(const float* __restrict__ row, F emit)
{
    float4 win4[qp_NL(Q)];
    #pragma unroll
    for (int i = 0; i < qp_NL(Q); i++)
        win4[i] = *(const float4*)(row + qp_W(Q) + 4*i);
    const float* win = (const float*)win4;
    SFor<0, 16>::run([&](auto jc) {
        constexpr int   j  = decltype(jc)::value;
        constexpr int   s  = qp_S(Q, j);
        constexpr int   xo = 16*Q + j;
        constexpr float w0 = qp_wt(xo, 0), w1 = qp_wt(xo, 1);
        constexpr float w2 = qp_wt(xo, 2), w3 = qp_wt(xo, 3);
        float v = fmaf(w0, win[s],
                  fmaf(w1, win[s+1],
                  fmaf(w2, win[s+2], w3 * win[s+3])));
        emit(j, v);
    });
}

// ---------------------------------------------------------------------------
// Keypoint block.
// ---------------------------------------------------------------------------
__device__ __forceinline__ void kp_block(
    int map_id, const float* __restrict__ maps, const float* __restrict__ rois,
    float* __restrict__ out)
{
    __shared__ __align__(16) float smap[HM * SROW];   // 13440 B
    __shared__ __align__(16) float tmpT[RESO * SROW]; // 15360 B ([xo][y])
    __shared__ float swv[8];
    __shared__ int   swi[8];

    const int tid = threadIdx.x;

    // Stage map into padded smem rows (float4; per-map offset 12544 B and
    // row stride 240 B are 16B multiples).
    {
        const float4* mp4 = (const float4*)(maps + (size_t)map_id * (HM * HM));
        #pragma unroll
        for (int i = 0; i < 4; i++) {
            int idx = tid + i * 256;
            if (idx < (HM * HM / 4)) {
                float4 v = __ldg(&mp4[idx]);
                int y = idx / 14, c = idx - y * 14;
                *(float4*)(smap + y * SROW + 4*c) = v;
            }
        }
    }
    __syncthreads();

    const int lane_o = tid & 63;
    const int q      = tid >> 6;              // warp-uniform

    // Stage 1: x-interp, transposed store tmpT[xo*SROW + y].
    if (lane_o < HM) {
        const float* row = smap + lane_o * SROW;
        float* tc = tmpT + lane_o;
        switch (q) {
        case 0: interp16<0>(row, [&](int j, float v){ tc[(   j)*SROW] = v; }); break;
        case 1: interp16<1>(row, [&](int j, float v){ tc[(16+j)*SROW] = v; }); break;
        case 2: interp16<2>(row, [&](int j, float v){ tc[(32+j)*SROW] = v; }); break;
        default:interp16<3>(row, [&](int j, float v){ tc[(48+j)*SROW] = v; }); break;
        }
    }
    __syncthreads();

    // Stage 2: y-interp + fused argmax. Track only j (SEL-imm); p built once.
    float best = -INFINITY; int bj = 0;
    {
        const float* row = tmpT + lane_o * SROW;
        switch (q) {
        case 0: interp16<0>(row, [&](int j, float v){
                    if (v > best) { best = v; bj = j; } }); break;
        case 1: interp16<1>(row, [&](int j, float v){
                    if (v > best) { best = v; bj = j; } }); break;
        case 2: interp16<2>(row, [&](int j, float v){
                    if (v > best) { best = v; bj = j; } }); break;
        default:interp16<3>(row, [&](int j, float v){
                    if (v > best) { best = v; bj = j; } }); break;
        }
    }
    int bidx = ((16*q + bj) << 6) | lane_o;   // p = yo*64 + xo

    #pragma unroll
    for (int o = 16; o; o >>= 1) {
        float ov = __shfl_xor_sync(0xffffffffu, best, o);
        int   oi = __shfl_xor_sync(0xffffffffu, bidx, o);
        if (ov > best || (ov == best && oi < bidx)) { best = ov; bidx = oi; }
    }
    if ((tid & 31) == 0) { swv[tid >> 5] = best; swi[tid >> 5] = bidx; }
    __syncthreads();

    if (tid == 0) {
        #pragma unroll
        for (int i = 1; i < 8; i++) {
            if (swv[i] > best || (swv[i] == best && swi[i] < bidx)) {
                best = swv[i]; bidx = swi[i];
            }
        }
        int r = map_id / K_KP;
        const float* rp = rois + r * 4;
        float x1 = rp[0], y1 = rp[1], x2 = rp[2], y2 = rp[3];
        float wc = fmaxf(x2 - x1, 1.f) * (1.f / (float)RESO);
        float hc = fmaxf(y2 - y1, 1.f) * (1.f / (float)RESO);
        int xi = bidx & 63, yi = bidx >> 6;
        float* xy = out + OFF_XY + (size_t)map_id * 3;
        xy[0] = (xi + 0.5f) * wc + x1;
        xy[1] = (yi + 0.5f) * hc + y1;
        xy[2] = 1.f;
        out[OFF_ES + map_id] = best;
    }
}

// ---------------------------------------------------------------------------
// Mask inference: float4 gather (plane offsets 16B-aligned), fast sigmoid,
// float2 stores (OFF_MASK is only 8B-aligned in the output).
// ---------------------------------------------------------------------------
__device__ __forceinline__ void mask_block(
    int mb, const float* __restrict__ mlog, const int* __restrict__ mlab,
    float* __restrict__ out)
{
    int idx = mb * 256 + threadIdx.x;          // float4 index < MASK_F4
    int r = idx / (MASK_HW / 4);
    int i = idx - r * (MASK_HW / 4);
    int lab = __ldg(&mlab[r]);
    float4 v = __ldg((const float4*)mlog + ((size_t)r * C_CLS + lab) * (MASK_HW / 4) + i);
    float2* o2 = (float2*)(out + OFF_MASK) + idx * 2;
    float2 a, b;
    a.x = 1.f / (1.f + __expf(-v.x));
    a.y = 1.f / (1.f + __expf(-v.y));
    b.x = 1.f / (1.f + __expf(-v.z));
    b.y = 1.f / (1.f + __expf(-v.w));
    o2[0] = a;
    o2[1] = b;
}

// ---------------------------------------------------------------------------
// FastRCNN loss partial block + last-block final reduction.
// ---------------------------------------------------------------------------
__device__ __forceinline__ void loss_block(
    int lb, const float* __restrict__ logits, const float* __restrict__ br,
    const int* __restrict__ labels, const float* __restrict__ tgt,
    float* __restrict__ out)
{
    __shared__ float scls[8], sbox[8];
    __shared__ int   is_last;
    int lane  = threadIdx.x & 31;
    int wid   = threadIdx.x >> 5;
    int gwarp = lb * 8 + wid;
    const int nwarps = LOSS_BLOCKS * 8;

    float cls_acc = 0.f, box_acc = 0.f;
    for (int row = gwarp; row < N_ROWS; row += nwarps) {
        const float* lp = logits + (size_t)row * C_CLS;
        int lab = labels[row];
        float v0 = (lane      < C_CLS) ? lp[lane]      : -INFINITY;
        float v1 = (lane + 32 < C_CLS) ? lp[lane + 32] : -INFINITY;
        float v2 = (lane + 64 < C_CLS) ? lp[lane + 64] : -INFINITY;
        float m = fmaxf(v0, fmaxf(v1, v2));
        #pragma unroll
        for (int o = 16; o; o >>= 1) m = fmaxf(m, __shfl_xor_sync(0xffffffffu, m, o));
        float s = 0.f;
        if (lane      < C_CLS) s += __expf(v0 - m);
        if (lane + 32 < C_CLS) s += __expf(v1 - m);
        if (lane + 64 < C_CLS) s += __expf(v2 - m);
        #pragma unroll
        for (int o = 16; o; o >>= 1) s += __shfl_xor_sync(0xffffffffu, s, o);
        float lv = -INFINITY;
        if (lane == lab)           lv = v0;
        else if (lane + 32 == lab) lv = v1;
        else if (lane + 64 == lab) lv = v2;
        #pragma unroll
        for (int o = 16; o; o >>= 1) lv = fmaxf(lv, __shfl_xor_sync(0xffffffffu, lv, o));
        cls_acc += (m + __logf(s)) - lv;

        if (lab > 0) {
            float sl = 0.f;
            if (lane < 4) {
                float d  = br[(size_t)row * (C_CLS * 4) + lab * 4 + lane] - tgt[row * 4 + lane];
                float ad = fabsf(d);
                sl = (ad < BETA) ? 0.5f * d * d / BETA : ad - 0.5f * BETA;
            }
            sl += __shfl_xor_sync(0xffffffffu, sl, 1);
            sl += __shfl_xor_sync(0xffffffffu, sl, 2);
            if (lane == 0) box_acc += sl;
        }
    }

    if (lane == 0) { scls[wid] = cls_acc; sbox[wid] = box_acc; }
    __syncthreads();
    if (threadIdx.x == 0) {
        float c = 0.f, b = 0.f;
        #pragma unroll
        for (int i = 0; i < 8; i++) { c += scls[i]; b += sbox[i]; }
        g_partials[lb * 2]     = c;
        g_partials[lb * 2 + 1] = b;
        __threadfence();
        is_last = (atomicAdd(&g_done, 1) == LOSS_BLOCKS - 1);
    }
    __syncthreads();

    if (is_last && threadIdx.x < 32) {
        __threadfence();
        float c = 0.f, b = 0.f;
        for (int i = lane; i < LOSS_BLOCKS; i += 32) {
            c += g_partials[2 * i];
            b += g_partials[2 * i + 1];
        }
        #pragma unroll
        for (int o = 16; o; o >>= 1) {
            c += __shfl_xor_sync(0xffffffffu, c, o);
            b += __shfl_xor_sync(0xffffffffu, b, o);
        }
        if (lane == 0) {
            out[0] = c * (1.f / (float)N_ROWS);
            out[1] = b * (1.f / (float)N_ROWS);
            g_done = 0;                       // reset for next graph replay
        }
    }
}

// ---------------------------------------------------------------------------
// Fused kernel: loss first (wave-1 completion of the cross-block reduction),
// then mask, then kp (uniform tail).
// ---------------------------------------------------------------------------
__global__ void __launch_bounds__(256) fused_kernel(
    const float* __restrict__ logits, const float* __restrict__ br,
    const int*   __restrict__ labels, const float* __restrict__ tgt,
    const float* __restrict__ kp_maps, const float* __restrict__ kp_rois,
    const float* __restrict__ mlog, const int* __restrict__ mlab,
    float* __restrict__ out)
{
    int b = blockIdx.x;
    if (b < LOSS_BLOCKS) {
        loss_block(b, logits, br, labels, tgt, out);
    } else if (b < LOSS_BLOCKS + MASK_BLOCKS) {
        mask_block(b - LOSS_BLOCKS, mlog, mlab, out);
    } else {
        kp_block(b - (LOSS_BLOCKS + MASK_BLOCKS), kp_maps, kp_rois, out);
    }
}

// ---------------------------------------------------------------------------
extern "C" void kernel_launch(void* const* d_in, const int* in_sizes, int n_in,
                              void* d_out, int out_size)
{
    const float* class_logits       = (const float*)d_in[0];
    const float* box_regression     = (const float*)d_in[1];
    const int*   labels             = (const int*)  d_in[2];
    const float* regression_targets = (const float*)d_in[3];
    const float* kp_maps            = (const float*)d_in[4];
    const float* kp_rois            = (const float*)d_in[5];
    const float* mask_logits        = (const float*)d_in[6];
    const int*   mask_labels        = (const int*)  d_in[7];
    float* out = (float*)d_out;

    fused_kernel<<<TOTAL_BLOCKS, 256>>>(class_logits, box_regression, labels,
                                        regression_targets, kp_maps, kp_rois,
                                        mask_logits, mask_labels, out);
}

// round 10
// speedup vs baseline: 3.4733x; 1.0711x over previous
#include <cuda_runtime.h>
#include <cstdint>
#include <math.h>

#define N_ROWS 4096
#define C_CLS  91
#define R_ROI  1024
#define K_KP   17
#define HM     56
#define RESO   64
#define BETA   (1.0f/9.0f)

#define OFF_XY   2
#define OFF_ES   (2 + R_ROI*K_KP*3)            /* 52226 */
#define OFF_MASK (OFF_ES + R_ROI*K_KP)         /* 69634 */
#define MASK_HW  784

#define MAPS_PER_CTA 4
#define KP_BLOCKS   (R_ROI * K_KP / MAPS_PER_CTA)  /* 4352 */
#define MASK_F4     (R_ROI * MASK_HW / 4)      /* 200704 float4 loads */
#define MASK_BLOCKS (MASK_F4 / 256)            /* 784 */
#define LOSS_BLOCKS 64
#define TOTAL_BLOCKS (LOSS_BLOCKS + MASK_BLOCKS + KP_BLOCKS)

#define SROW 60                                 /* padded row stride (floats) */

__device__ float g_partials[2 * LOSS_BLOCKS];
__device__ int   g_done = 0;

// ---------------------------------------------------------------------------
// Compile-time bicubic 56->64 resample parameters (jax.image.resize
// semantics: half-pixel sampling, Keys a=-0.5, OOB taps dropped + renorm).
// s(xo) = (14*xo - 1)/16 exactly.
// ---------------------------------------------------------------------------
__host__ __device__ constexpr int qp_floor(int xo) {
    int num = 14 * xo - 1;
    return (num >= 0) ? num / 16 : -((-num + 15) / 16);
}
__host__ __device__ constexpr int qp_base(int xo) {
    int b = qp_floor(xo) - 1;
    return (b < 0) ? 0 : ((b > HM - 4) ? (HM - 4) : b);
}
__host__ __device__ constexpr int qp_W(int Q)  { return Q==0?0 : Q==1?12 : Q==2?24 : 40; }
__host__ __device__ constexpr int qp_NL(int Q) { return (Q==1 || Q==2) ? 5 : 4; }
__host__ __device__ constexpr int qp_S(int Q, int j) { return qp_base(16*Q + j) - qp_W(Q); }

__host__ __device__ constexpr float qp_cubic(int dn16) {   // t = |dn16|/16
    float t = (float)(dn16 < 0 ? -dn16 : dn16) / 16.0f;
    return (t < 1.0f) ? ((1.5f*t - 2.5f)*t)*t + 1.0f
         : (t < 2.0f) ? ((-0.5f*t + 2.5f)*t - 4.0f)*t + 2.0f
         : 0.0f;
}
__host__ __device__ constexpr float qp_wsum(int xo) {
    float s = 0.f;
    for (int k = qp_floor(xo) - 1; k <= qp_floor(xo) + 2; ++k)
        if (k >= 0 && k < HM) s += qp_cubic(14*xo - 1 - 16*k);
    return s;
}
__host__ __device__ constexpr float qp_wt(int xo, int slot) {
    int k = qp_base(xo) + slot;
    if (k < qp_floor(xo) - 1 || k > qp_floor(xo) + 2 || k < 0 || k >= HM)
        return 0.0f;
    return qp_cubic(14*xo - 1 - 16*k) * (1.0f / qp_wsum(xo));
}

// C++11-safe compile-time for.
template<int J, int N> struct SFor {
    template<typename F> __device__ __forceinline__ static void run(F&& f) {
        f(J_tag()); SFor<J+1, N>::run(f);
    }
    struct J_tag { static constexpr int value = J; };
};
template<int N> struct SFor<N, N> {
    template<typename F> __device__ __forceinline__ static void run(F&&) {}
};

// Interpolate 16 consecutive outputs (xo = 16Q..16Q+15) of one line.
// All weights are FFMA immediates.
template<int Q, typename F>
__device__ __forceinline__ void interp16(const float* __restrict__ row, F emit)
{
    float4 win4[qp_NL(Q)];
    #pragma unroll
    for (int i = 0; i < qp_NL(Q); i++)
        win4[i] = *(const float4*)(row + qp_W(Q) + 4*i);
    const float* win = (const float*)win4;
    SFor<0, 16>::run([&](auto jc) {
        constexpr int   j  = decltype(jc)::value;
        constexpr int   s  = qp_S(Q, j);
        constexpr int   xo = 16*Q + j;
        constexpr float w0 = qp_wt(xo, 0), w1 = qp_wt(xo, 1);
        constexpr float w2 = qp_wt(xo, 2), w3 = qp_wt(xo, 3);
        float v = fmaf(w0, win[s],
                  fmaf(w1, win[s+1],
                  fmaf(w2, win[s+2], w3 * win[s+3])));
        emit(j, v);
    });
}

// ---------------------------------------------------------------------------
// Keypoint multi-map block: 4 maps per CTA, cp.async single-buffer prefetch
// (stage 2 never reads smap, so the next map streams in behind it).
// ---------------------------------------------------------------------------
__device__ __forceinline__ void kp_multi(
    int map_base, const float* __restrict__ maps, const float* __restrict__ rois,
    float* __restrict__ out)
{
    __shared__ __align__(16) float smap[HM * SROW];   // 13440 B
    __shared__ __align__(16) float tmpT[RESO * SROW]; // 15360 B ([xo][y])
    __shared__ float swv[8];
    __shared__ int   swi[8];

    const int tid = threadIdx.x;
    const int lane_o = tid & 63;
    const int q      = tid >> 6;              // warp-uniform

    // Per-thread staging slots (idx < 784): dst smem offset, computed once.
    int  s_y0 = (tid)        / 14, s_c0 = (tid)        - s_y0 * 14;
    int  s_y1 = (tid + 256)  / 14, s_c1 = (tid + 256)  - s_y1 * 14;
    int  s_y2 = (tid + 512)  / 14, s_c2 = (tid + 512)  - s_y2 * 14;
    bool has3 = (tid + 768) < 784;            // tid < 16
    int  s_y3 = (tid + 768)  / 14, s_c3 = (tid + 768)  - s_y3 * 14;
    unsigned d0 = (unsigned)__cvta_generic_to_shared(smap + s_y0 * SROW + 4*s_c0);
    unsigned d1 = (unsigned)__cvta_generic_to_shared(smap + s_y1 * SROW + 4*s_c1);
    unsigned d2 = (unsigned)__cvta_generic_to_shared(smap + s_y2 * SROW + 4*s_c2);
    unsigned d3 = (unsigned)__cvta_generic_to_shared(smap + s_y3 * SROW + 4*s_c3);

    auto stage_load = [&](int mid) {
        const char* src = (const char*)(maps + (size_t)mid * (HM * HM));
        asm volatile("cp.async.cg.shared.global [%0], [%1], 16;"
                     :: "r"(d0), "l"(src + (size_t)tid * 16) : "memory");
        asm volatile("cp.async.cg.shared.global [%0], [%1], 16;"
                     :: "r"(d1), "l"(src + (size_t)(tid + 256) * 16) : "memory");
        asm volatile("cp.async.cg.shared.global [%0], [%1], 16;"
                     :: "r"(d2), "l"(src + (size_t)(tid + 512) * 16) : "memory");
        if (has3)
            asm volatile("cp.async.cg.shared.global [%0], [%1], 16;"
                         :: "r"(d3), "l"(src + (size_t)(tid + 768) * 16) : "memory");
        asm volatile("cp.async.commit_group;" ::: "memory");
    };

    stage_load(map_base);
    asm volatile("cp.async.wait_group 0;" ::: "memory");
    __syncthreads();

    #pragma unroll 1
    for (int m = 0; m < MAPS_PER_CTA; m++) {
        const int map_id = map_base + m;

        // Stage 1: x-interp, transposed store tmpT[xo*SROW + y].
        if (lane_o < HM) {
            const float* row = smap + lane_o * SROW;
            float* tc = tmpT + lane_o;
            switch (q) {
            case 0: interp16<0>(row, [&](int j, float v){ tc[(   j)*SROW] = v; }); break;
            case 1: interp16<1>(row, [&](int j, float v){ tc[(16+j)*SROW] = v; }); break;
            case 2: interp16<2>(row, [&](int j, float v){ tc[(32+j)*SROW] = v; }); break;
            default:interp16<3>(row, [&](int j, float v){ tc[(48+j)*SROW] = v; }); break;
            }
        }
        __syncthreads();                       // tmpT ready; smap reads done

        // Prefetch next map into smap, hidden behind stage 2.
        if (m + 1 < MAPS_PER_CTA) stage_load(map_base + m + 1);

        // Stage 2: y-interp + fused argmax (track j only; p built once).
        float best = -INFINITY; int bj = 0;
        {
            const float* row = tmpT + lane_o * SROW;
            switch (q) {
            case 0: interp16<0>(row, [&](int j, float v){
                        if (v > best) { best = v; bj = j; } }); break;
            case 1: interp16<1>(row, [&](int j, float v){
                        if (v > best) { best = v; bj = j; } }); break;
            case 2: interp16<2>(row, [&](int j, float v){
                        if (v > best) { best = v; bj = j; } }); break;
            default:interp16<3>(row, [&](int j, float v){
                        if (v > best) { best = v; bj = j; } }); break;
            }
        }
        int bidx = ((16*q + bj) << 6) | lane_o;   // p = yo*64 + xo

        #pragma unroll
        for (int o = 16; o; o >>= 1) {
            float ov = __shfl_xor_sync(0xffffffffu, best, o);
            int   oi = __shfl_xor_sync(0xffffffffu, bidx, o);
            if (ov > best || (ov == best && oi < bidx)) { best = ov; bidx = oi; }
        }
        if ((tid & 31) == 0) { swv[tid >> 5] = best; swi[tid >> 5] = bidx; }
        __syncthreads();                       // reduction bar

        if (tid == 0) {
            #pragma unroll
            for (int i = 1; i < 8; i++) {
                if (swv[i] > best || (swv[i] == best && swi[i] < bidx)) {
                    best = swv[i]; bidx = swi[i];
                }
            }
            int r = map_id / K_KP;
            const float* rp = rois + r * 4;
            float x1 = rp[0], y1 = rp[1], x2 = rp[2], y2 = rp[3];
            float wc = fmaxf(x2 - x1, 1.f) * (1.f / (float)RESO);
            float hc = fmaxf(y2 - y1, 1.f) * (1.f / (float)RESO);
            int xi = bidx & 63, yi = bidx >> 6;
            float* xy = out + OFF_XY + (size_t)map_id * 3;
            xy[0] = (xi + 0.5f) * wc + x1;
            xy[1] = (yi + 0.5f) * hc + y1;
            xy[2] = 1.f;
            out[OFF_ES + map_id] = best;
        }

        asm volatile("cp.async.wait_group 0;" ::: "memory");
        __syncthreads();                       // smap refilled; swv/swi free
    }
}

// ---------------------------------------------------------------------------
// Mask inference: float4 gather, fast sigmoid, float2 stores (OFF_MASK is
// only 8B-aligned in the output).
// ---------------------------------------------------------------------------
__device__ __forceinline__ void mask_block(
    int mb, const float* __restrict__ mlog, const int* __restrict__ mlab,
    float* __restrict__ out)
{
    int idx = mb * 256 + threadIdx.x;          // float4 index < MASK_F4
    int r = idx / (MASK_HW / 4);
    int i = idx - r * (MASK_HW / 4);
    int lab = __ldg(&mlab[r]);
    float4 v = __ldg((const float4*)mlog + ((size_t)r * C_CLS + lab) * (MASK_HW / 4) + i);
    float2* o2 = (float2*)(out + OFF_MASK) + idx * 2;
    float2 a, b;
    a.x = __fdividef(1.f, 1.f + __expf(-v.x));
    a.y = __fdividef(1.f, 1.f + __expf(-v.y));
    b.x = __fdividef(1.f, 1.f + __expf(-v.z));
    b.y = __fdividef(1.f, 1.f + __expf(-v.w));
    o2[0] = a;
    o2[1] = b;
}

// ---------------------------------------------------------------------------
// FastRCNN loss partial block + last-block final reduction (deterministic).
// ---------------------------------------------------------------------------
__device__ __forceinline__ void loss_block(
    int lb, const float* __restrict__ logits, const float* __restrict__ br,
    const int* __restrict__ labels, const float* __restrict__ tgt,
    float* __restrict__ out)
{
    __shared__ float scls[8], sbox[8];
    __shared__ int   is_last;
    int lane  = threadIdx.x & 31;
    int wid   = threadIdx.x >> 5;
    int gwarp = lb * 8 + wid;
    const int nwarps = LOSS_BLOCKS * 8;

    float cls_acc = 0.f, box_acc = 0.f;
    for (int row = gwarp; row < N_ROWS; row += nwarps) {
        const float* lp = logits + (size_t)row * C_CLS;
        int lab = labels[row];
        float v0 = (lane      < C_CLS) ? lp[lane]      : -INFINITY;
        float v1 = (lane + 32 < C_CLS) ? lp[lane + 32] : -INFINITY;
        float v2 = (lane + 64 < C_CLS) ? lp[lane + 64] : -INFINITY;
        float m = fmaxf(v0, fmaxf(v1, v2));
        #pragma unroll
        for (int o = 16; o; o >>= 1) m = fmaxf(m, __shfl_xor_sync(0xffffffffu, m, o));
        float s = 0.f;
        if (lane      < C_CLS) s += __expf(v0 - m);
        if (lane + 32 < C_CLS) s += __expf(v1 - m);
        if (lane + 64 < C_CLS) s += __expf(v2 - m);
        #pragma unroll
        for (int o = 16; o; o >>= 1) s += __shfl_xor_sync(0xffffffffu, s, o);
        float lv = -INFINITY;
        if (lane == lab)           lv = v0;
        else if (lane + 32 == lab) lv = v1;
        else if (lane + 64 == lab) lv = v2;
        #pragma unroll
        for (int o = 16; o; o >>= 1) lv = fmaxf(lv, __shfl_xor_sync(0xffffffffu, lv, o));
        cls_acc += (m + __logf(s)) - lv;

        if (lab > 0) {
            float sl = 0.f;
            if (lane < 4) {
                float d  = br[(size_t)row * (C_CLS * 4) + lab * 4 + lane] - tgt[row * 4 + lane];
                float ad = fabsf(d);
                sl = (ad < BETA) ? 0.5f * d * d / BETA : ad - 0.5f * BETA;
            }
            sl += __shfl_xor_sync(0xffffffffu, sl, 1);
            sl += __shfl_xor_sync(0xffffffffu, sl, 2);
            if (lane == 0) box_acc += sl;
        }
    }

    if (lane == 0) { scls[wid] = cls_acc; sbox[wid] = box_acc; }
    __syncthreads();
    if (threadIdx.x == 0) {
        float c = 0.f, b = 0.f;
        #pragma unroll
        for (int i = 0; i < 8; i++) { c += scls[i]; b += sbox[i]; }
        g_partials[lb * 2]     = c;
        g_partials[lb * 2 + 1] = b;
        __threadfence();
        is_last = (atomicAdd(&g_done, 1) == LOSS_BLOCKS - 1);
    }
    __syncthreads();

    if (is_last && threadIdx.x < 32) {
        __threadfence();
        float c = 0.f, b = 0.f;
        for (int i = lane; i < LOSS_BLOCKS; i += 32) {
            c += g_partials[2 * i];
            b += g_partials[2 * i + 1];
        }
        #pragma unroll
        for (int o = 16; o; o >>= 1) {
            c += __shfl_xor_sync(0xffffffffu, c, o);
            b += __shfl_xor_sync(0xffffffffu, b, o);
        }
        if (lane == 0) {
            out[0] = c * (1.f / (float)N_ROWS);
            out[1] = b * (1.f / (float)N_ROWS);
            g_done = 0;                       // reset for next graph replay
        }
    }
}

// ---------------------------------------------------------------------------
// Fused kernel: loss first, then mask, then multi-map kp.
// ---------------------------------------------------------------------------
__global__ void __launch_bounds__(256) fused_kernel(
    const float* __restrict__ logits, const float* __restrict__ br,
    const int*   __restrict__ labels, const float* __restrict__ tgt,
    const float* __restrict__ kp_maps, const float* __restrict__ kp_rois,
    const float* __restrict__ mlog, const int* __restrict__ mlab,
    float* __restrict__ out)
{
    int b = blockIdx.x;
    if (b < LOSS_BLOCKS) {
        loss_block(b, logits, br, labels, tgt, out);
    } else if (b < LOSS_BLOCKS + MASK_BLOCKS) {
        mask_block(b - LOSS_BLOCKS, mlog, mlab, out);
    } else {
        kp_multi((b - (LOSS_BLOCKS + MASK_BLOCKS)) * MAPS_PER_CTA,
                 kp_maps, kp_rois, out);
    }
}

// ---------------------------------------------------------------------------
extern "C" void kernel_launch(void* const* d_in, const int* in_sizes, int n_in,
                              void* d_out, int out_size)
{
    const float* class_logits       = (const float*)d_in[0];
    const float* box_regression     = (const float*)d_in[1];
    const int*   labels             = (const int*)  d_in[2];
    const float* regression_targets = (const float*)d_in[3];
    const float* kp_maps            = (const float*)d_in[4];
    const float* kp_rois            = (const float*)d_in[5];
    const float* mask_logits        = (const float*)d_in[6];
    const int*   mask_labels        = (const int*)  d_in[7];
    float* out = (float*)d_out;

    fused_kernel<<<TOTAL_BLOCKS, 256>>>(class_logits, box_regression, labels,
                                        regression_targets, kp_maps, kp_rois,
                                        mask_logits, mask_labels, out);
}